// round 3
// baseline (speedup 1.0000x reference)
#include <cuda_runtime.h>
#include <math.h>

#define M_TOK 64000

// ---------------- scratch ----------------------------------------------------
__device__ float g_A0[M_TOK * 120];
__device__ float g_B [M_TOK * 160];
__device__ float g_Gpart[500 * 121 * 140];
__device__ float g_Gpart2[10 * 121 * 140];
__device__ float g_Gb[121 * 160];
__device__ float g_T1[121 * 160];
__device__ float g_attn[160 * 160];
__device__ float g_P[160 * 160];
__device__ float g_r[160];
__device__ float g_sA0part[250 * 120];
__device__ float g_sA0[120];

// ---------------- packed fp32 helpers ----------------------------------------
__device__ __forceinline__ void fma2(unsigned long long& d,
                                     unsigned long long a,
                                     unsigned long long b) {
    asm("fma.rn.f32x2 %0, %1, %2, %0;" : "+l"(d) : "l"(a), "l"(b));
}
__device__ __forceinline__ void unpk(unsigned long long v, float& lo, float& hi) {
    asm("mov.b64 {%0, %1}, %2;" : "=f"(lo), "=f"(hi) : "l"(v));
}

// ---------------- branch traits ----------------------------------------------
template <int BR> struct BT;
template <> struct BT<0> { // axi
    static constexpr int D = 140, ND = 120, NDP = 121;
    static constexpr int W0 = 5, W1 = 7, W2 = 4;
    static constexpr int S0 = 48, S1 = 66, S2 = 38;
    static constexpr int PB0 = 1, PB1 = 2, PB2 = 1;
    static constexpr int OUT_OFF = 0;
    static constexpr int IG = 16, JG = 35, KC = 28;
};
template <> struct BT<1> { // cor view (38,38,66)
    static constexpr int D = 112, ND = 48, NDP = 49;
    static constexpr int W0 = 4, W1 = 4, W2 = 7;
    static constexpr int S0 = 38, S1 = 38, S2 = 66;
    static constexpr int PB0 = 1, PB1 = 1, PB2 = 2;
    static constexpr int OUT_OFF = 7704576;
    static constexpr int IG = 7, JG = 28, KC = 28;
};
template <> struct BT<2> { // sag view (38,78,48)
    static constexpr int D = 160, ND = 36, NDP = 37;
    static constexpr int W0 = 4, W1 = 8, W2 = 5;
    static constexpr int S0 = 38, S1 = 78, S2 = 48;
    static constexpr int PB0 = 1, PB1 = 1, PB2 = 1;
    static constexpr int OUT_OFF = 13804032;
    static constexpr int IG = 5, JG = 40, KC = 32;
};

template <int BR> __device__ __forceinline__ int raw_index(int c, int z0, int z1, int z2);
template <> __device__ __forceinline__ int raw_index<0>(int c, int z0, int z1, int z2) {
    return ((c * 48 + z0) * 66 + z1) * 38 + z2;
}
template <> __device__ __forceinline__ int raw_index<1>(int c, int z0, int z1, int z2) {
    return ((c * 38 + z0) * 66 + z2) * 38 + z1;
}
template <> __device__ __forceinline__ int raw_index<2>(int c, int z0, int z1, int z2) {
    return ((c * 48 + z2) * 78 + z1) * 38 + z0;
}

template <int BR> __device__ __forceinline__ int distcol(int u);
template <> __device__ __forceinline__ int distcol<0>(int u) { return u; }
template <> __device__ __forceinline__ int distcol<1>(int u) {
    int u0 = u / 12, u1 = (u % 12) / 4, u2 = u % 4;
    return (u0 * 6 + 2 * u1) * 4 + u2;
}
template <> __device__ __forceinline__ int distcol<2>(int u) {
    int u0 = u / 9, u1 = (u % 9) / 3, u2 = u % 3;
    return (u0 * 6 + 2 * u1) * 4 + u2;
}

template <int BR> __device__ __forceinline__ void imaps(int i, int& u, int& bc);
template <> __device__ __forceinline__ void imaps<0>(int i, int& u, int& bc) {
    int b0 = i / 28, r = i % 28, b1 = r / 4, b2 = r % 4;
    int m1 = b1 ? b1 - 1 : 0;
    u = (b0 * 6 + m1) * 4 + b2;  bc = u;
}
template <> __device__ __forceinline__ void imaps<1>(int i, int& u, int& bc) {
    int b0 = i / 28, r = i % 28, b1 = r / 7, b2 = r % 7;
    int v1 = b1 ? b1 - 1 : 0;  int v2 = b2 >> 1;
    u = (b0 * 3 + v1) * 4 + v2;  bc = (b0 * 6 + 2 * v1) * 4 + v2;
}
template <> __device__ __forceinline__ void imaps<2>(int i, int& u, int& bc) {
    int b0 = i / 40, r = i % 40, b1 = r / 5, b2 = r % 5;
    int v1 = (b1 < 4) ? 0 : ((b1 - 2) >> 1);
    int v2 = (b2 < 2) ? 0 : ((b2 < 3) ? 1 : 2);
    u = (b0 * 3 + v1) * 3 + v2;  bc = (b0 * 6 + 2 * v1) * 4 + v2;
}

// ---------------- builds (4 cols/thread + shared LUT) -------------------------
__global__ void k_build_A0(const float* __restrict__ atlas) {
    __shared__ int s0[120], s1[120], s2[120];
    int tid = threadIdx.x;
    if (tid < 120) {
        int b0 = tid / 24, b1 = (tid / 4) % 6, b2 = tid % 4;
        s0[tid] = b0 - 2; s1[tid] = b1 - 2; s2[tid] = b2 - 1;
    }
    __syncthreads();
    int gid = blockIdx.x * blockDim.x + tid;           // M_TOK*30 exact
    int m = gid / 30, q = gid % 30;
    int c = m / 1000, rm_ = m % 1000;
    int i0 = rm_ / 100, i1 = (rm_ / 10) % 10, i2 = rm_ % 10;
    int z0b = i0 * 5, z1b = i1 * 6, z2b = i2 * 4;
    float4 o;
    float* op = (float*)&o;
#pragma unroll
    for (int e = 0; e < 4; e++) {
        int col = 4 * q + e;
        int z0 = z0b + s0[col], z1 = z1b + s1[col], z2 = z2b + s2[col];
        float v = 0.f;
        if ((unsigned)z0 < 46u && (unsigned)z1 < 56u && (unsigned)z2 < 38u)
            v = atlas[((c * 46 + z0) * 56 + z1) * 38 + z2];
        op[e] = v;
    }
    *(float4*)&g_A0[m * 120 + 4 * q] = o;
}

__global__ void k_sA0_part() {
    int c = threadIdx.x;
    if (c >= 120) return;
    int m0 = blockIdx.x * 256;
    float s = 0.f;
    for (int k = 0; k < 256; k++) s += g_A0[(m0 + k) * 120 + c];
    g_sA0part[blockIdx.x * 120 + c] = s;
}
__global__ void k_sA0_red() {
    int c = threadIdx.x;
    if (c >= 120) return;
    float s = 0.f;
    for (int p = 0; p < 250; p++) s += g_sA0part[p * 120 + c];
    g_sA0[c] = s;
}

template <int BR> __global__ void k_build_B(const float* __restrict__ in) {
    using T = BT<BR>;
    constexpr int Q = T::D / 4;
    __shared__ int s0[T::D], s1[T::D], s2[T::D];
    int tid = threadIdx.x;
    if (tid < T::D) {
        int b0 = tid / (T::W1 * T::W2), rc = tid % (T::W1 * T::W2);
        int b1 = rc / T::W2, b2 = rc % T::W2;
        s0[tid] = b0 - T::PB0; s1[tid] = b1 - T::PB1; s2[tid] = b2 - T::PB2;
    }
    __syncthreads();
    int gid = blockIdx.x * blockDim.x + tid;           // M_TOK*Q exact
    int m = gid / Q, q = gid % Q;
    int c = m / 1000, rm_ = m % 1000;
    int i0 = rm_ / 100, i1 = (rm_ / 10) % 10, i2 = rm_ % 10;
    int z0b = i0 * T::W0, z1b = i1 * T::W1, z2b = i2 * T::W2;
    float4 o;
    float* op = (float*)&o;
#pragma unroll
    for (int e = 0; e < 4; e++) {
        int col = 4 * q + e;
        int z0 = z0b + s0[col], z1 = z1b + s1[col], z2 = z2b + s2[col];
        float v = 0.f;
        if ((unsigned)z0 < (unsigned)T::S0 && (unsigned)z1 < (unsigned)T::S1 &&
            (unsigned)z2 < (unsigned)T::S2)
            v = in[raw_index<BR>(c, z0, z1, z2)];
        op[e] = v;
    }
    *(float4*)&g_B[m * T::D + 4 * q] = o;
}

// ---------------- Gram GEMM (split-K 500x128, FFMA2, deterministic) -----------
template <int BR> __global__ __launch_bounds__(BT<BR>::IG* BT<BR>::JG) void k_gemmG() {
    using T = BT<BR>;
    constexpr int IG = T::IG, JG = T::JG, PADI = IG * 8, NT = IG * JG;
    __shared__ __align__(16) float As[8][PADI];
    __shared__ __align__(16) float Bsd[8][2 * T::D];   // duplicated pairs
    int tid = threadIdx.x;
    int jg = tid % JG, ig = tid / JG;

    unsigned long long acc2[4][4];
#pragma unroll
    for (int r = 0; r < 4; r++)
#pragma unroll
        for (int cc = 0; cc < 4; cc++) acc2[r][cc] = 0ULL;

    int m0 = blockIdx.x * 128;
    for (int kc = 0; kc < 16; kc++) {
        int mb = m0 + kc * 8;
        for (int t = tid; t < 8 * PADI; t += NT) {
            int k = t / PADI, u = t % PADI;
            float v;
            if (u < T::ND)       v = g_A0[(mb + k) * 120 + distcol<BR>(u)];
            else if (u == T::ND) v = 1.0f;
            else                 v = 0.0f;
            As[k][u] = v;
        }
        for (int t = tid; t < 8 * T::D; t += NT) {
            int k = t / T::D, j = t % T::D;
            float v = g_B[(mb + k) * T::D + j];
            *(float2*)&Bsd[k][2 * j] = make_float2(v, v);
        }
        __syncthreads();
#pragma unroll
        for (int k = 0; k < 8; k++) {
            ulonglong2 a01 = *(const ulonglong2*)&As[k][ig * 8];
            ulonglong2 a23 = *(const ulonglong2*)&As[k][ig * 8 + 4];
            ulonglong2 b01 = *(const ulonglong2*)&Bsd[k][8 * jg];
            ulonglong2 b23 = *(const ulonglong2*)&Bsd[k][8 * jg + 4];
            unsigned long long a[4] = {a01.x, a01.y, a23.x, a23.y};
            unsigned long long b[4] = {b01.x, b01.y, b23.x, b23.y};
#pragma unroll
            for (int r = 0; r < 4; r++)
#pragma unroll
                for (int cc = 0; cc < 4; cc++) fma2(acc2[r][cc], a[r], b[cc]);
        }
        __syncthreads();
    }
    int base = blockIdx.x * (T::NDP * T::D);
#pragma unroll
    for (int r = 0; r < 4; r++) {
        int u0 = ig * 8 + 2 * r;
#pragma unroll
        for (int cc = 0; cc < 4; cc++) {
            float lo, hi;
            unpk(acc2[r][cc], lo, hi);
            if (u0 < T::NDP)     g_Gpart[base + u0 * T::D + jg * 4 + cc] = lo;
            if (u0 + 1 < T::NDP) g_Gpart[base + (u0 + 1) * T::D + jg * 4 + cc] = hi;
        }
    }
}

// two-stage reduction of split-K partials (deterministic)
template <int BR> __global__ void k_reduceG1() {
    using T = BT<BR>;
    constexpr int N4 = T::NDP * T::D / 4;
    int idx4 = blockIdx.x * blockDim.x + threadIdx.x;
    if (idx4 >= N4) return;
    int g = blockIdx.y;
    float4 s = make_float4(0.f, 0.f, 0.f, 0.f);
#pragma unroll 5
    for (int p = g * 50; p < g * 50 + 50; p++) {
        float4 v = *(const float4*)&g_Gpart[p * T::NDP * T::D + idx4 * 4];
        s.x += v.x; s.y += v.y; s.z += v.z; s.w += v.w;
    }
    *(float4*)&g_Gpart2[g * T::NDP * T::D + idx4 * 4] = s;
}
template <int BR> __global__ void k_reduceG2() {
    using T = BT<BR>;
    constexpr int N4 = T::NDP * T::D / 4;
    int idx4 = blockIdx.x * blockDim.x + threadIdx.x;
    if (idx4 >= N4) return;
    float4 s = make_float4(0.f, 0.f, 0.f, 0.f);
#pragma unroll
    for (int g = 0; g < 10; g++) {
        float4 v = *(const float4*)&g_Gpart2[g * T::NDP * T::D + idx4 * 4];
        s.x += v.x; s.y += v.y; s.z += v.z; s.w += v.w;
    }
    *(float4*)&g_Gb[idx4 * 4] = s;
}

// ---------------- T1 = Gb * Wk ------------------------------------------------
template <int BR> __global__ void k_T1(const float* __restrict__ Wk) {
    using T = BT<BR>;
    __shared__ float grow[T::D];
    int u = blockIdx.x, j = threadIdx.x;
    grow[j] = g_Gb[u * T::D + j];
    __syncthreads();
    float s = 0.f;
#pragma unroll 4
    for (int jp = 0; jp < T::D; jp++) s += grow[jp] * Wk[jp * T::D + j];
    g_T1[u * T::D + j] = s;
}

// ---------------- S, softmax, r ----------------------------------------------
template <int BR> __global__ void k_S(const float* __restrict__ Wq,
                                      const float* __restrict__ bq,
                                      const float* __restrict__ bk,
                                      const float* __restrict__ bv) {
    using T = BT<BR>;
    constexpr int D = T::D;
    __shared__ float red[256];
    __shared__ int   rm_s[D];
    __shared__ float sc[3];
    int i = blockIdx.x, j = threadIdx.x;
    int uj, bcj; imaps<BR>(j, uj, bcj);
    rm_s[j] = uj;

    red[j] = Wq[j * D + i] * g_sA0[bcj];
    for (int p = D + j; p < 256; p += D) red[p] = 0.f;
    __syncthreads();
    for (int st = 128; st > 0; st >>= 1) {
        if (j < st) red[j] += red[j + st];
        __syncthreads();
    }
    if (j == 0) sc[0] = red[0];
    __syncthreads();

    float s = 0.f;
#pragma unroll 4
    for (int i2 = 0; i2 < D; i2++)
        s += Wq[i2 * D + i] * g_T1[rm_s[i2] * D + j];
    float bkj = bk[j];
    s += sc[0] * bkj + bq[i] * (g_T1[T::ND * D + j] + 64000.0f * bkj);

    red[j] = s;
    for (int p = D + j; p < 256; p += D) red[p] = -3.4e38f;
    __syncthreads();
    for (int st = 128; st > 0; st >>= 1) {
        if (j < st) red[j] = fmaxf(red[j], red[j + st]);
        __syncthreads();
    }
    if (j == 0) sc[1] = red[0];
    __syncthreads();
    float e = expf(s - sc[1]);
    red[j] = e;
    for (int p = D + j; p < 256; p += D) red[p] = 0.f;
    __syncthreads();
    for (int st = 128; st > 0; st >>= 1) {
        if (j < st) red[j] += red[j + st];
        __syncthreads();
    }
    if (j == 0) sc[2] = red[0];
    __syncthreads();
    float inv = 1.0f / sc[2];
    g_attn[i * D + j] = e * inv;

    red[j] = e * bv[j];
    for (int p = D + j; p < 256; p += D) red[p] = 0.f;
    __syncthreads();
    for (int st = 128; st > 0; st >>= 1) {
        if (j < st) red[j] += red[j + st];
        __syncthreads();
    }
    if (j == 0) g_r[i] = red[0] * inv;
}

// ---------------- P[l][i] = sum_j Wv[l][j] attn[i][j] -------------------------
template <int BR> __global__ void k_P(const float* __restrict__ Wv) {
    using T = BT<BR>;
    __shared__ float arow[T::D];
    int i = blockIdx.x, l = threadIdx.x;
    arow[l] = g_attn[i * T::D + l];
    __syncthreads();
    float p = 0.f;
#pragma unroll 4
    for (int jj = 0; jj < T::D; jj++) p += Wv[l * T::D + jj] * arow[jj];
    g_P[l * T::D + i] = p;
}

// ---------------- cross = B*P + r (FFMA2, k-chunked), fold+crop+scatter -------
template <int BR> __global__ __launch_bounds__(16 * BT<BR>::JG)
void k_cross(float* __restrict__ out) {
    using T = BT<BR>;
    constexpr int D = T::D, JG = T::JG, NT = 16 * JG, KC = T::KC;
    constexpr int NCH = D / KC;
    constexpr int BSROW = 132;
    extern __shared__ __align__(16) float dynsm[];
    float* Bs  = dynsm;                   // [KC][BSROW] (m-major, transposed)
    float* Psd = Bs + KC * BSROW;         // [KC][2*D]   (duplicated pairs)
    float* rs  = Psd + KC * 2 * D;        // [D]

    int tid = threadIdx.x;
    int jg = tid % JG, ig = tid / JG;
    int m0 = blockIdx.x * 128;
    int mb = ig * 8, jb = jg * 4;

    for (int t = tid; t < D; t += NT) rs[t] = g_r[t];

    unsigned long long acc2[4][4];
#pragma unroll
    for (int r = 0; r < 4; r++)
#pragma unroll
        for (int cc = 0; cc < 4; cc++) acc2[r][cc] = 0ULL;

    for (int ch = 0; ch < NCH; ch++) {
        int k0 = ch * KC;
        for (int t = tid; t < 128 * (KC / 4); t += NT) {
            int mm = t / (KC / 4), kv = t % (KC / 4);
            float4 v = *(const float4*)&g_B[(m0 + mm) * D + k0 + kv * 4];
            Bs[(kv * 4 + 0) * BSROW + mm] = v.x;
            Bs[(kv * 4 + 1) * BSROW + mm] = v.y;
            Bs[(kv * 4 + 2) * BSROW + mm] = v.z;
            Bs[(kv * 4 + 3) * BSROW + mm] = v.w;
        }
        for (int t = tid; t < KC * (D / 4); t += NT) {
            int r = t / (D / 4), kv = t % (D / 4);
            float4 v = *(const float4*)&g_P[(k0 + r) * D + kv * 4];
            *(float2*)&Psd[r * 2 * D + 2 * (kv * 4 + 0)] = make_float2(v.x, v.x);
            *(float2*)&Psd[r * 2 * D + 2 * (kv * 4 + 1)] = make_float2(v.y, v.y);
            *(float2*)&Psd[r * 2 * D + 2 * (kv * 4 + 2)] = make_float2(v.z, v.z);
            *(float2*)&Psd[r * 2 * D + 2 * (kv * 4 + 3)] = make_float2(v.w, v.w);
        }
        __syncthreads();
#pragma unroll 4
        for (int k = 0; k < KC; k++) {
            ulonglong2 a01 = *(const ulonglong2*)&Bs[k * BSROW + mb];
            ulonglong2 a23 = *(const ulonglong2*)&Bs[k * BSROW + mb + 4];
            ulonglong2 b01 = *(const ulonglong2*)&Psd[k * 2 * D + 8 * jg];
            ulonglong2 b23 = *(const ulonglong2*)&Psd[k * 2 * D + 8 * jg + 4];
            unsigned long long a[4] = {a01.x, a01.y, a23.x, a23.y};
            unsigned long long b[4] = {b01.x, b01.y, b23.x, b23.y};
#pragma unroll
            for (int r = 0; r < 4; r++)
#pragma unroll
                for (int cc = 0; cc < 4; cc++) fma2(acc2[r][cc], a[r], b[cc]);
        }
        __syncthreads();
    }

#pragma unroll
    for (int r2 = 0; r2 < 4; r2++) {
        float va[4][2];
#pragma unroll
        for (int cc = 0; cc < 4; cc++) unpk(acc2[r2][cc], va[cc][0], va[cc][1]);
#pragma unroll
        for (int h = 0; h < 2; h++) {
            int m = m0 + mb + 2 * r2 + h;
            int c = m / 1000, rm_ = m % 1000;
            int i0 = rm_ / 100, i1 = (rm_ / 10) % 10, i2 = rm_ % 10;
            int z0b = i0 * T::W0 - T::PB0;
            int z1b = i1 * T::W1 - T::PB1;
            int z2b = i2 * T::W2 - T::PB2;
#pragma unroll
            for (int cc = 0; cc < 4; cc++) {
                int i = jb + cc;
                int b0 = i / (T::W1 * T::W2), rc = i % (T::W1 * T::W2);
                int b1 = rc / T::W2, b2 = rc % T::W2;
                int z0 = z0b + b0, z1 = z1b + b1, z2 = z2b + b2;
                if ((unsigned)z0 < (unsigned)T::S0 && (unsigned)z1 < (unsigned)T::S1 &&
                    (unsigned)z2 < (unsigned)T::S2)
                    out[T::OUT_OFF + raw_index<BR>(c, z0, z1, z2)] = va[cc][h] + rs[i];
            }
        }
    }
}

// ---------------- host --------------------------------------------------------
template <int BR>
static void run_branch(const float* in, const float* Wq, const float* bq,
                       const float* Wk, const float* bk,
                       const float* Wv, const float* bv, float* out) {
    using T = BT<BR>;
    constexpr int N4 = T::NDP * T::D / 4;
    constexpr int RBX = (N4 + 255) / 256;
    k_build_B<BR><<<(M_TOK * (T::D / 4)) / 256, 256>>>(in);
    k_gemmG<BR><<<500, T::IG * T::JG>>>();
    k_reduceG1<BR><<<dim3(RBX, 10), 256>>>();
    k_reduceG2<BR><<<RBX, 256>>>();
    k_T1<BR><<<T::NDP, T::D>>>(Wk);
    k_S<BR><<<T::D, T::D>>>(Wq, bq, bk, bv);
    k_P<BR><<<T::D, T::D>>>(Wv);
    constexpr int SMEM = (T::KC * 132 + T::KC * 2 * T::D + T::D) * 4;
    cudaFuncSetAttribute(k_cross<BR>, cudaFuncAttributeMaxDynamicSharedMemorySize, SMEM);
    k_cross<BR><<<500, 16 * T::JG, SMEM>>>(out);
}

extern "C" void kernel_launch(void* const* d_in, const int* in_sizes, int n_in,
                              void* d_out, int out_size) {
    (void)in_sizes; (void)n_in; (void)out_size;
    const float* axi   = (const float*)d_in[0];
    const float* cor   = (const float*)d_in[1];
    const float* sag   = (const float*)d_in[2];
    const float* atlas = (const float*)d_in[3];
    float* out = (float*)d_out;

    k_build_A0<<<(M_TOK * 30) / 256, 256>>>(atlas);
    k_sA0_part<<<250, 128>>>();
    k_sA0_red<<<1, 128>>>();

    run_branch<0>(axi, (const float*)d_in[4],  (const float*)d_in[5],
                       (const float*)d_in[6],  (const float*)d_in[7],
                       (const float*)d_in[8],  (const float*)d_in[9],  out);
    run_branch<1>(cor, (const float*)d_in[10], (const float*)d_in[11],
                       (const float*)d_in[12], (const float*)d_in[13],
                       (const float*)d_in[14], (const float*)d_in[15], out);
    run_branch<2>(sag, (const float*)d_in[16], (const float*)d_in[17],
                       (const float*)d_in[18], (const float*)d_in[19],
                       (const float*)d_in[20], (const float*)d_in[21], out);
}

// round 6
// speedup vs baseline: 1.2712x; 1.2712x over previous
#include <cuda_runtime.h>
#include <math.h>

#define M_TOK 64000

// ---------------- scratch ----------------------------------------------------
__device__ float g_A0[M_TOK * 120];
__device__ float g_B [M_TOK * 160];
__device__ float g_Gpart[500 * 121 * 140];
__device__ float g_Gpart2[10 * 121 * 140];
__device__ float g_Gb[121 * 160];
__device__ float g_T1[121 * 160];
__device__ float g_attn[160 * 160];
__device__ float g_P[160 * 160];
__device__ float g_r[160];
__device__ float g_sA0part[250 * 120];
__device__ float g_sA0[120];

// ---------------- tf32 helpers ------------------------------------------------
__device__ __forceinline__ unsigned f2tf(float x) {
    unsigned r;
    asm("cvt.rna.tf32.f32 %0, %1;" : "=r"(r) : "f"(x));
    return r;
}
__device__ __forceinline__ void mma_tf32(float* c, const unsigned* a,
                                         unsigned b0, unsigned b1) {
    asm volatile(
        "mma.sync.aligned.m16n8k8.row.col.f32.tf32.tf32.f32 "
        "{%0,%1,%2,%3}, {%4,%5,%6,%7}, {%8,%9}, {%0,%1,%2,%3};"
        : "+f"(c[0]), "+f"(c[1]), "+f"(c[2]), "+f"(c[3])
        : "r"(a[0]), "r"(a[1]), "r"(a[2]), "r"(a[3]), "r"(b0), "r"(b1));
}

// ---------------- branch traits ----------------------------------------------
template <int BR> struct BT;
template <> struct BT<0> { // axi
    static constexpr int D = 140, ND = 120, NDP = 121;
    static constexpr int W0 = 5, W1 = 7, W2 = 4;
    static constexpr int S0 = 48, S1 = 66, S2 = 38;
    static constexpr int PB0 = 1, PB1 = 2, PB2 = 1;
    static constexpr int OUT_OFF = 0;
};
template <> struct BT<1> { // cor view (38,38,66)
    static constexpr int D = 112, ND = 48, NDP = 49;
    static constexpr int W0 = 4, W1 = 4, W2 = 7;
    static constexpr int S0 = 38, S1 = 38, S2 = 66;
    static constexpr int PB0 = 1, PB1 = 1, PB2 = 2;
    static constexpr int OUT_OFF = 7704576;
};
template <> struct BT<2> { // sag view (38,78,48)
    static constexpr int D = 160, ND = 36, NDP = 37;
    static constexpr int W0 = 4, W1 = 8, W2 = 5;
    static constexpr int S0 = 38, S1 = 78, S2 = 48;
    static constexpr int PB0 = 1, PB1 = 1, PB2 = 1;
    static constexpr int OUT_OFF = 13804032;
};

template <int BR> __device__ __forceinline__ int raw_index(int c, int z0, int z1, int z2);
template <> __device__ __forceinline__ int raw_index<0>(int c, int z0, int z1, int z2) {
    return ((c * 48 + z0) * 66 + z1) * 38 + z2;
}
template <> __device__ __forceinline__ int raw_index<1>(int c, int z0, int z1, int z2) {
    return ((c * 38 + z0) * 66 + z2) * 38 + z1;
}
template <> __device__ __forceinline__ int raw_index<2>(int c, int z0, int z1, int z2) {
    return ((c * 48 + z2) * 78 + z1) * 38 + z0;
}

template <int BR> __device__ __forceinline__ int distcol(int u);
template <> __device__ __forceinline__ int distcol<0>(int u) { return u; }
template <> __device__ __forceinline__ int distcol<1>(int u) {
    int u0 = u / 12, u1 = (u % 12) / 4, u2 = u % 4;
    return (u0 * 6 + 2 * u1) * 4 + u2;
}
template <> __device__ __forceinline__ int distcol<2>(int u) {
    int u0 = u / 9, u1 = (u % 9) / 3, u2 = u % 3;
    return (u0 * 6 + 2 * u1) * 4 + u2;
}

template <int BR> __device__ __forceinline__ void imaps(int i, int& u, int& bc);
template <> __device__ __forceinline__ void imaps<0>(int i, int& u, int& bc) {
    int b0 = i / 28, r = i % 28, b1 = r / 4, b2 = r % 4;
    int m1 = b1 ? b1 - 1 : 0;
    u = (b0 * 6 + m1) * 4 + b2;  bc = u;
}
template <> __device__ __forceinline__ void imaps<1>(int i, int& u, int& bc) {
    int b0 = i / 28, r = i % 28, b1 = r / 7, b2 = r % 7;
    int v1 = b1 ? b1 - 1 : 0;  int v2 = b2 >> 1;
    u = (b0 * 3 + v1) * 4 + v2;  bc = (b0 * 6 + 2 * v1) * 4 + v2;
}
template <> __device__ __forceinline__ void imaps<2>(int i, int& u, int& bc) {
    int b0 = i / 40, r = i % 40, b1 = r / 5, b2 = r % 5;
    int v1 = (b1 < 4) ? 0 : ((b1 - 2) >> 1);
    int v2 = (b2 < 2) ? 0 : ((b2 < 3) ? 1 : 2);
    u = (b0 * 3 + v1) * 3 + v2;  bc = (b0 * 6 + 2 * v1) * 4 + v2;
}

// ---------------- builds ------------------------------------------------------
__global__ void k_build_A0(const float* __restrict__ atlas) {
    __shared__ int s0[120], s1[120], s2[120];
    int tid = threadIdx.x;
    if (tid < 120) {
        int b0 = tid / 24, b1 = (tid / 4) % 6, b2 = tid % 4;
        s0[tid] = b0 - 2; s1[tid] = b1 - 2; s2[tid] = b2 - 1;
    }
    __syncthreads();
    int gid = blockIdx.x * blockDim.x + tid;
    int m = gid / 30, q = gid % 30;
    int c = m / 1000, rm_ = m % 1000;
    int i0 = rm_ / 100, i1 = (rm_ / 10) % 10, i2 = rm_ % 10;
    int z0b = i0 * 5, z1b = i1 * 6, z2b = i2 * 4;
    float4 o;
    float* op = (float*)&o;
#pragma unroll
    for (int e = 0; e < 4; e++) {
        int col = 4 * q + e;
        int z0 = z0b + s0[col], z1 = z1b + s1[col], z2 = z2b + s2[col];
        float v = 0.f;
        if ((unsigned)z0 < 46u && (unsigned)z1 < 56u && (unsigned)z2 < 38u)
            v = atlas[((c * 46 + z0) * 56 + z1) * 38 + z2];
        op[e] = v;
    }
    *(float4*)&g_A0[m * 120 + 4 * q] = o;
}

__global__ void k_sA0_part() {
    int c = threadIdx.x;
    if (c >= 120) return;
    int m0 = blockIdx.x * 256;
    float s = 0.f;
    for (int k = 0; k < 256; k++) s += g_A0[(m0 + k) * 120 + c];
    g_sA0part[blockIdx.x * 120 + c] = s;
}
__global__ void k_sA0_red() {
    int c = threadIdx.x;
    if (c >= 120) return;
    float s = 0.f;
    for (int p = 0; p < 250; p++) s += g_sA0part[p * 120 + c];
    g_sA0[c] = s;
}

template <int BR> __global__ void k_build_B(const float* __restrict__ in) {
    using T = BT<BR>;
    constexpr int Q = T::D / 4;
    __shared__ int s0[T::D], s1[T::D], s2[T::D];
    int tid = threadIdx.x;
    if (tid < T::D) {
        int b0 = tid / (T::W1 * T::W2), rc = tid % (T::W1 * T::W2);
        int b1 = rc / T::W2, b2 = rc % T::W2;
        s0[tid] = b0 - T::PB0; s1[tid] = b1 - T::PB1; s2[tid] = b2 - T::PB2;
    }
    __syncthreads();
    int gid = blockIdx.x * blockDim.x + tid;
    int m = gid / Q, q = gid % Q;
    int c = m / 1000, rm_ = m % 1000;
    int i0 = rm_ / 100, i1 = (rm_ / 10) % 10, i2 = rm_ % 10;
    int z0b = i0 * T::W0, z1b = i1 * T::W1, z2b = i2 * T::W2;
    float4 o;
    float* op = (float*)&o;
#pragma unroll
    for (int e = 0; e < 4; e++) {
        int col = 4 * q + e;
        int z0 = z0b + s0[col], z1 = z1b + s1[col], z2 = z2b + s2[col];
        float v = 0.f;
        if ((unsigned)z0 < (unsigned)T::S0 && (unsigned)z1 < (unsigned)T::S1 &&
            (unsigned)z2 < (unsigned)T::S2)
            v = in[raw_index<BR>(c, z0, z1, z2)];
        op[e] = v;
    }
    *(float4*)&g_B[m * T::D + 4 * q] = o;
}

// ---------------- Gram GEMM via tf32 mma (3xTF32), split-K 250x256 -------------
// Output tile: 128 u-rows (covers all NDP<=121 gram rows) x DP cols.
// 8 warps: 4(m=u) x 2(n).  k = tokens, 16 per k-iter.
template <int BR> __global__ __launch_bounds__(256)
void k_gramG_mma() {
    using T = BT<BR>;
    constexpr int D   = T::D;
    constexpr int DP  = (D + 7) / 8 * 8;                 // 144/112/160
    constexpr int NTW = DP / 16;                         // n8-tiles per warp
    constexpr int ALD = 136;                             // 128 + 8 pad
    constexpr int BLD = DP + ((8 - DP % 32) + 32) % 32;  // ≡8 mod 32

    __shared__ float Ah[16 * ALD], Al[16 * ALD];         // [k(m)][u]
    __shared__ float Bh[16 * BLD], Bl[16 * BLD];         // [k(m)][j]
    __shared__ int dcol[128];

    int tid  = threadIdx.x;
    int lane = tid & 31, wid = tid >> 5;
    int wm = wid >> 1, wn = wid & 1;
    int l4 = lane >> 2, lm4 = lane & 3;
    int m0 = blockIdx.x * 256;

    if (tid < 128) {
        int u = tid;
        dcol[u] = (u < T::ND) ? distcol<BR>(u) : ((u == T::ND) ? -1 : -2);
    }

    float acc[2][NTW][4];
#pragma unroll
    for (int mt = 0; mt < 2; mt++)
#pragma unroll
        for (int nt = 0; nt < NTW; nt++)
#pragma unroll
            for (int e = 0; e < 4; e++) acc[mt][nt][e] = 0.f;

    for (int kc = 0; kc < 16; kc++) {
        int mb = m0 + kc * 16;
        __syncthreads();
        // A tile (transposed gather through dcol)
        for (int t = tid; t < 16 * 128; t += 256) {
            int k = t >> 7, u = t & 127;
            int dc = dcol[u];
            float x = (dc >= 0) ? g_A0[(mb + k) * 120 + dc]
                                : ((dc == -1) ? 1.0f : 0.0f);
            unsigned hb = f2tf(x);
            float hf = __uint_as_float(hb);
            unsigned lb = f2tf(x - hf);
            Ah[k * ALD + u] = hf;
            Al[k * ALD + u] = __uint_as_float(lb);
        }
        // B tile (native layout)
        for (int t = tid; t < 16 * DP; t += 256) {
            int k = t / DP, j = t % DP;
            float x = (j < D) ? g_B[(mb + k) * D + j] : 0.f;
            unsigned hb = f2tf(x);
            float hf = __uint_as_float(hb);
            unsigned lb = f2tf(x - hf);
            Bh[k * BLD + j] = hf;
            Bl[k * BLD + j] = __uint_as_float(lb);
        }
        __syncthreads();

#pragma unroll
        for (int ks = 0; ks < 2; ks++) {
            int kb = ks * 8;
            unsigned ah[2][4], al[2][4];
#pragma unroll
            for (int mt = 0; mt < 2; mt++) {
                int r_ = wm * 32 + mt * 16 + l4;
                int c_ = kb + lm4;
                ah[mt][0] = __float_as_uint(Ah[c_ * ALD + r_]);
                ah[mt][1] = __float_as_uint(Ah[c_ * ALD + r_ + 8]);
                ah[mt][2] = __float_as_uint(Ah[(c_ + 4) * ALD + r_]);
                ah[mt][3] = __float_as_uint(Ah[(c_ + 4) * ALD + r_ + 8]);
                al[mt][0] = __float_as_uint(Al[c_ * ALD + r_]);
                al[mt][1] = __float_as_uint(Al[c_ * ALD + r_ + 8]);
                al[mt][2] = __float_as_uint(Al[(c_ + 4) * ALD + r_]);
                al[mt][3] = __float_as_uint(Al[(c_ + 4) * ALD + r_ + 8]);
            }
#pragma unroll
            for (int nt = 0; nt < NTW; nt++) {
                int n_ = wn * (DP / 2) + nt * 8 + l4;
                int k_ = kb + lm4;
                unsigned bh0 = __float_as_uint(Bh[k_ * BLD + n_]);
                unsigned bh1 = __float_as_uint(Bh[(k_ + 4) * BLD + n_]);
                unsigned bl0 = __float_as_uint(Bl[k_ * BLD + n_]);
                unsigned bl1 = __float_as_uint(Bl[(k_ + 4) * BLD + n_]);
#pragma unroll
                for (int mt = 0; mt < 2; mt++) {
                    mma_tf32(acc[mt][nt], ah[mt], bh0, bh1);
                    mma_tf32(acc[mt][nt], ah[mt], bl0, bl1);
                    mma_tf32(acc[mt][nt], al[mt], bh0, bh1);
                }
            }
        }
    }

    // partials out (deterministic reduction downstream)
    int base = blockIdx.x * (T::NDP * D);
#pragma unroll
    for (int mt = 0; mt < 2; mt++)
#pragma unroll
        for (int half = 0; half < 2; half++) {
            int u = wm * 32 + mt * 16 + l4 + half * 8;
            if (u < T::NDP) {
#pragma unroll
                for (int nt = 0; nt < NTW; nt++)
#pragma unroll
                    for (int e = 0; e < 2; e++) {
                        int j = wn * (DP / 2) + nt * 8 + 2 * lm4 + e;
                        if (j < D)
                            g_Gpart[base + u * D + j] = acc[mt][nt][half * 2 + e];
                    }
            }
        }
}

// two-stage reduction of 250 split-K partials (deterministic)
template <int BR> __global__ void k_reduceG1() {
    using T = BT<BR>;
    constexpr int N4 = T::NDP * T::D / 4;
    int idx4 = blockIdx.x * blockDim.x + threadIdx.x;
    if (idx4 >= N4) return;
    int g = blockIdx.y;
    float4 s = make_float4(0.f, 0.f, 0.f, 0.f);
#pragma unroll 5
    for (int p = g * 25; p < g * 25 + 25; p++) {
        float4 v = *(const float4*)&g_Gpart[p * T::NDP * T::D + idx4 * 4];
        s.x += v.x; s.y += v.y; s.z += v.z; s.w += v.w;
    }
    *(float4*)&g_Gpart2[g * T::NDP * T::D + idx4 * 4] = s;
}
template <int BR> __global__ void k_reduceG2() {
    using T = BT<BR>;
    constexpr int N4 = T::NDP * T::D / 4;
    int idx4 = blockIdx.x * blockDim.x + threadIdx.x;
    if (idx4 >= N4) return;
    float4 s = make_float4(0.f, 0.f, 0.f, 0.f);
#pragma unroll
    for (int g = 0; g < 10; g++) {
        float4 v = *(const float4*)&g_Gpart2[g * T::NDP * T::D + idx4 * 4];
        s.x += v.x; s.y += v.y; s.z += v.z; s.w += v.w;
    }
    *(float4*)&g_Gb[idx4 * 4] = s;
}

// ---------------- T1 = Gb * Wk ------------------------------------------------
template <int BR> __global__ void k_T1(const float* __restrict__ Wk) {
    using T = BT<BR>;
    __shared__ float grow[T::D];
    int u = blockIdx.x, j = threadIdx.x;
    grow[j] = g_Gb[u * T::D + j];
    __syncthreads();
    float s = 0.f;
#pragma unroll 4
    for (int jp = 0; jp < T::D; jp++) s += grow[jp] * Wk[jp * T::D + j];
    g_T1[u * T::D + j] = s;
}

// ---------------- S, softmax, r ----------------------------------------------
template <int BR> __global__ void k_S(const float* __restrict__ Wq,
                                      const float* __restrict__ bq,
                                      const float* __restrict__ bk,
                                      const float* __restrict__ bv) {
    using T = BT<BR>;
    constexpr int D = T::D;
    __shared__ float red[256];
    __shared__ int   rm_s[D];
    __shared__ float sc[3];
    int i = blockIdx.x, j = threadIdx.x;
    int uj, bcj; imaps<BR>(j, uj, bcj);
    rm_s[j] = uj;

    red[j] = Wq[j * D + i] * g_sA0[bcj];
    for (int p = D + j; p < 256; p += D) red[p] = 0.f;
    __syncthreads();
    for (int st = 128; st > 0; st >>= 1) {
        if (j < st) red[j] += red[j + st];
        __syncthreads();
    }
    if (j == 0) sc[0] = red[0];
    __syncthreads();

    float s = 0.f;
#pragma unroll 4
    for (int i2 = 0; i2 < D; i2++)
        s += Wq[i2 * D + i] * g_T1[rm_s[i2] * D + j];
    float bkj = bk[j];
    s += sc[0] * bkj + bq[i] * (g_T1[T::ND * D + j] + 64000.0f * bkj);

    red[j] = s;
    for (int p = D + j; p < 256; p += D) red[p] = -3.4e38f;
    __syncthreads();
    for (int st = 128; st > 0; st >>= 1) {
        if (j < st) red[j] = fmaxf(red[j], red[j + st]);
        __syncthreads();
    }
    if (j == 0) sc[1] = red[0];
    __syncthreads();
    float e = expf(s - sc[1]);
    red[j] = e;
    for (int p = D + j; p < 256; p += D) red[p] = 0.f;
    __syncthreads();
    for (int st = 128; st > 0; st >>= 1) {
        if (j < st) red[j] += red[j + st];
        __syncthreads();
    }
    if (j == 0) sc[2] = red[0];
    __syncthreads();
    float inv = 1.0f / sc[2];
    g_attn[i * D + j] = e * inv;

    red[j] = e * bv[j];
    for (int p = D + j; p < 256; p += D) red[p] = 0.f;
    __syncthreads();
    for (int st = 128; st > 0; st >>= 1) {
        if (j < st) red[j] += red[j + st];
        __syncthreads();
    }
    if (j == 0) g_r[i] = red[0] * inv;
}

// ---------------- P[l][i] = sum_j Wv[l][j] attn[i][j] -------------------------
template <int BR> __global__ void k_P(const float* __restrict__ Wv) {
    using T = BT<BR>;
    __shared__ float arow[T::D];
    int i = blockIdx.x, l = threadIdx.x;
    arow[l] = g_attn[i * T::D + l];
    __syncthreads();
    float p = 0.f;
#pragma unroll 4
    for (int jj = 0; jj < T::D; jj++) p += Wv[l * T::D + jj] * arow[jj];
    g_P[l * T::D + i] = p;
}

// ---------------- cross = B*P + r via tf32 mma (3xTF32), fold+scatter ---------
template <int BR> __global__ __launch_bounds__(256)
void k_cross_mma(float* __restrict__ out) {
    using T = BT<BR>;
    constexpr int D   = T::D;
    constexpr int DP  = (D + 7) / 8 * 8;
    constexpr int NCH = DP / 16;
    constexpr int NTW = DP / 16;
    constexpr int ALD = 136;
    constexpr int PLD = DP + ((8 - DP % 32) + 32) % 32;

    __shared__ float Ah[16 * ALD], Al[16 * ALD];
    __shared__ float Ph[16 * PLD], Pl[16 * PLD];
    __shared__ float rs[D];
    __shared__ int   cs0[D], cs1[D], cs2[D];

    int tid  = threadIdx.x;
    int lane = tid & 31, wid = tid >> 5;
    int wm = wid >> 1, wn = wid & 1;
    int l4 = lane >> 2, lm4 = lane & 3;
    int m0 = blockIdx.x * 128;

    for (int t = tid; t < D; t += 256) {
        int b0 = t / (T::W1 * T::W2), rc = t % (T::W1 * T::W2);
        cs0[t] = b0 - T::PB0;
        cs1[t] = rc / T::W2 - T::PB1;
        cs2[t] = rc % T::W2 - T::PB2;
        rs[t]  = g_r[t];
    }

    float acc[2][NTW][4];
#pragma unroll
    for (int mt = 0; mt < 2; mt++)
#pragma unroll
        for (int nt = 0; nt < NTW; nt++)
#pragma unroll
            for (int e = 0; e < 4; e++) acc[mt][nt][e] = 0.f;

    for (int ch = 0; ch < NCH; ch++) {
        int k0 = ch * 16;
        __syncthreads();
        {
            int t = tid;
#pragma unroll
            for (int it = 0; it < 2; it++, t += 256) {
                int mm = t >> 2, kq = (t & 3) * 4;
                int gk = k0 + kq;
                float4 v = make_float4(0.f, 0.f, 0.f, 0.f);
                if (gk < D) v = *(const float4*)&g_B[(m0 + mm) * D + gk];
                float xs[4] = {v.x, v.y, v.z, v.w};
#pragma unroll
                for (int e = 0; e < 4; e++) {
                    unsigned hb = f2tf(xs[e]);
                    float hf = __uint_as_float(hb);
                    unsigned lb = f2tf(xs[e] - hf);
                    Ah[(kq + e) * ALD + mm] = hf;
                    Al[(kq + e) * ALD + mm] = __uint_as_float(lb);
                }
            }
        }
        for (int t = tid; t < 16 * DP; t += 256) {
            int r = t / DP, n = t % DP;
            float x = 0.f;
            if (n < D && k0 + r < D) x = g_P[(k0 + r) * D + n];
            unsigned hb = f2tf(x);
            float hf = __uint_as_float(hb);
            unsigned lb = f2tf(x - hf);
            Ph[r * PLD + n] = hf;
            Pl[r * PLD + n] = __uint_as_float(lb);
        }
        __syncthreads();

#pragma unroll
        for (int ks = 0; ks < 2; ks++) {
            int kb = ks * 8;
            unsigned ah[2][4], al[2][4];
#pragma unroll
            for (int mt = 0; mt < 2; mt++) {
                int r_ = wm * 32 + mt * 16 + l4;
                int c_ = kb + lm4;
                ah[mt][0] = __float_as_uint(Ah[c_ * ALD + r_]);
                ah[mt][1] = __float_as_uint(Ah[c_ * ALD + r_ + 8]);
                ah[mt][2] = __float_as_uint(Ah[(c_ + 4) * ALD + r_]);
                ah[mt][3] = __float_as_uint(Ah[(c_ + 4) * ALD + r_ + 8]);
                al[mt][0] = __float_as_uint(Al[c_ * ALD + r_]);
                al[mt][1] = __float_as_uint(Al[c_ * ALD + r_ + 8]);
                al[mt][2] = __float_as_uint(Al[(c_ + 4) * ALD + r_]);
                al[mt][3] = __float_as_uint(Al[(c_ + 4) * ALD + r_ + 8]);
            }
#pragma unroll
            for (int nt = 0; nt < NTW; nt++) {
                int n_ = wn * (DP / 2) + nt * 8 + l4;
                int k_ = kb + lm4;
                unsigned bh0 = __float_as_uint(Ph[k_ * PLD + n_]);
                unsigned bh1 = __float_as_uint(Ph[(k_ + 4) * PLD + n_]);
                unsigned bl0 = __float_as_uint(Pl[k_ * PLD + n_]);
                unsigned bl1 = __float_as_uint(Pl[(k_ + 4) * PLD + n_]);
#pragma unroll
                for (int mt = 0; mt < 2; mt++) {
                    mma_tf32(acc[mt][nt], ah[mt], bh0, bh1);
                    mma_tf32(acc[mt][nt], ah[mt], bl0, bl1);
                    mma_tf32(acc[mt][nt], al[mt], bh0, bh1);
                }
            }
        }
    }

#pragma unroll
    for (int mt = 0; mt < 2; mt++) {
#pragma unroll
        for (int half = 0; half < 2; half++) {
            int m = m0 + wm * 32 + mt * 16 + l4 + half * 8;
            int c = m / 1000, rm_ = m % 1000;
            int i0 = rm_ / 100, i1 = (rm_ / 10) % 10, i2 = rm_ % 10;
            int z0b = i0 * T::W0, z1b = i1 * T::W1, z2b = i2 * T::W2;
#pragma unroll
            for (int nt = 0; nt < NTW; nt++) {
#pragma unroll
                for (int e = 0; e < 2; e++) {
                    int i = wn * (DP / 2) + nt * 8 + 2 * lm4 + e;
                    if (i < D) {
                        float v = acc[mt][nt][half * 2 + e];
                        int z0 = z0b + cs0[i], z1 = z1b + cs1[i], z2 = z2b + cs2[i];
                        if ((unsigned)z0 < (unsigned)T::S0 &&
                            (unsigned)z1 < (unsigned)T::S1 &&
                            (unsigned)z2 < (unsigned)T::S2)
                            out[T::OUT_OFF + raw_index<BR>(c, z0, z1, z2)] = v + rs[i];
                    }
                }
            }
        }
    }
}

// ---------------- host --------------------------------------------------------
template <int BR>
static void run_branch(const float* in, const float* Wq, const float* bq,
                       const float* Wk, const float* bk,
                       const float* Wv, const float* bv, float* out) {
    using T = BT<BR>;
    constexpr int N4 = T::NDP * T::D / 4;
    constexpr int RBX = (N4 + 255) / 256;
    k_build_B<BR><<<(M_TOK * (T::D / 4)) / 256, 256>>>(in);
    k_gramG_mma<BR><<<250, 256>>>();
    k_reduceG1<BR><<<dim3(RBX, 10), 256>>>();
    k_reduceG2<BR><<<RBX, 256>>>();
    k_T1<BR><<<T::NDP, T::D>>>(Wk);
    k_S<BR><<<T::D, T::D>>>(Wq, bq, bk, bv);
    k_P<BR><<<T::D, T::D>>>(Wv);
    k_cross_mma<BR><<<500, 256>>>(out);
}

extern "C" void kernel_launch(void* const* d_in, const int* in_sizes, int n_in,
                              void* d_out, int out_size) {
    (void)in_sizes; (void)n_in; (void)out_size;
    const float* axi   = (const float*)d_in[0];
    const float* cor   = (const float*)d_in[1];
    const float* sag   = (const float*)d_in[2];
    const float* atlas = (const float*)d_in[3];
    float* out = (float*)d_out;

    k_build_A0<<<(M_TOK * 30) / 256, 256>>>(atlas);
    k_sA0_part<<<250, 128>>>();
    k_sA0_red<<<1, 128>>>();

    run_branch<0>(axi, (const float*)d_in[4],  (const float*)d_in[5],
                       (const float*)d_in[6],  (const float*)d_in[7],
                       (const float*)d_in[8],  (const float*)d_in[9],  out);
    run_branch<1>(cor, (const float*)d_in[10], (const float*)d_in[11],
                       (const float*)d_in[12], (const float*)d_in[13],
                       (const float*)d_in[14], (const float*)d_in[15], out);
    run_branch<2>(sag, (const float*)d_in[16], (const float*)d_in[17],
                       (const float*)d_in[18], (const float*)d_in[19],
                       (const float*)d_in[20], (const float*)d_in[21], out);
}